// round 1
// baseline (speedup 1.0000x reference)
#include <cuda_runtime.h>
#include <math.h>

// ---------------- problem dims ----------------
#define B_   8
#define L_   256
#define N_   1024
#define M_   8
#define E_   16384
#define C_   50
#define EMB_ 768
#define D_   256
#define TD_  50
#define NN_  1025           // N+1
#define KS_  512            // K_SPLIT
#define NLROWS 32768        // B*KS*M logic rows

// ---------------- device scratch ----------------
__device__ float    g_text[B_ * EMB_];
__device__ float    g_rows[NLROWS * EMB_];       // gathered logic rows; reused for MLP output
__device__ float    g_hid[NLROWS * 1024];
__device__ float    g_X[B_ * N_ * EMB_];         // pooled pre-ntw
__device__ float    g_NE[B_ * N_ * EMB_];
__device__ float    g_CAT[B_ * NN_ * EMB_];
__device__ float    g_H[B_ * NN_ * D_];
__device__ float    g_Q[B_ * NN_ * D_];
__device__ float    g_Kb[B_ * NN_ * D_];
__device__ float    g_V[B_ * NN_ * D_];
__device__ float    g_TP[100 * D_];
__device__ float    g_KET[2 * TD_ * D_];
__device__ float    g_LBUF[B_ * E_ * 4];
__device__ unsigned g_MXE[B_ * NN_ * 4];
__device__ float    g_DEN[B_ * NN_ * 4];
__device__ float    g_AGG[B_ * NN_ * D_];
__device__ float    g_W2C[C_ * 1280];
__device__ float    g_B2[C_];

// ---------------- float ordered-encoding for atomicMax ----------------
__device__ __forceinline__ unsigned fenc(float f) {
    unsigned u = __float_as_uint(f);
    return (u & 0x80000000u) ? ~u : (u | 0x80000000u);
}
__device__ __forceinline__ float fdec(unsigned u) {
    unsigned v = (u & 0x80000000u) ? (u & 0x7fffffffu) : ~u;
    return __uint_as_float(v);
}

// ---------------- generic 128x128x16 SGEMM, 8x8 register tile ----------------
template<bool RELU, bool BIAS>
__global__ __launch_bounds__(256) void sgemm128(
    const float* __restrict__ A, const float* __restrict__ Bm,
    const float* __restrict__ bias, float* __restrict__ Cmat,
    int Mr, int Nc, int Kd)
{
    __shared__ __align__(16) float As[16][132];
    __shared__ __align__(16) float Bs[16][128];
    const int tid = threadIdx.x;
    const int tx = tid & 15, ty = tid >> 4;
    const int rowBase = blockIdx.y * 128;
    const int colBase = blockIdx.x * 128;

    float acc[8][8];
#pragma unroll
    for (int i = 0; i < 8; i++)
#pragma unroll
        for (int j = 0; j < 8; j++) acc[i][j] = 0.f;

    for (int k0 = 0; k0 < Kd; k0 += 16) {
#pragma unroll
        for (int i = 0; i < 2; i++) {
            int v = tid + i * 256;
            int r = v >> 2, c4 = (v & 3) * 4;
            int grow = rowBase + r;
            float4 f = make_float4(0.f, 0.f, 0.f, 0.f);
            if (grow < Mr) f = *(const float4*)(A + (size_t)grow * Kd + k0 + c4);
            As[c4 + 0][r] = f.x; As[c4 + 1][r] = f.y;
            As[c4 + 2][r] = f.z; As[c4 + 3][r] = f.w;
        }
#pragma unroll
        for (int i = 0; i < 2; i++) {
            int v = tid + i * 256;
            int r = v >> 5, c4 = (v & 31) * 4;
            *(float4*)(&Bs[r][c4]) = *(const float4*)(Bm + (size_t)(k0 + r) * Nc + colBase + c4);
        }
        __syncthreads();
#pragma unroll
        for (int kk = 0; kk < 16; kk++) {
            float4 a0 = *(const float4*)(&As[kk][ty * 4]);
            float4 a1 = *(const float4*)(&As[kk][64 + ty * 4]);
            float4 b0 = *(const float4*)(&Bs[kk][tx * 4]);
            float4 b1 = *(const float4*)(&Bs[kk][64 + tx * 4]);
            float ar[8] = {a0.x, a0.y, a0.z, a0.w, a1.x, a1.y, a1.z, a1.w};
            float br[8] = {b0.x, b0.y, b0.z, b0.w, b1.x, b1.y, b1.z, b1.w};
#pragma unroll
            for (int i = 0; i < 8; i++)
#pragma unroll
                for (int j = 0; j < 8; j++) acc[i][j] += ar[i] * br[j];
        }
        __syncthreads();
    }

#pragma unroll
    for (int i = 0; i < 8; i++) {
        int grow = rowBase + ((i < 4) ? (ty * 4 + i) : (64 + ty * 4 + i - 4));
        if (grow >= Mr) continue;
#pragma unroll
        for (int jf = 0; jf < 2; jf++) {
            int gcol = colBase + ((jf == 0) ? (tx * 4) : (64 + tx * 4));
            float o0 = acc[i][jf * 4 + 0], o1 = acc[i][jf * 4 + 1];
            float o2 = acc[i][jf * 4 + 2], o3 = acc[i][jf * 4 + 3];
            if (BIAS) {
                o0 += bias[gcol + 0]; o1 += bias[gcol + 1];
                o2 += bias[gcol + 2]; o3 += bias[gcol + 3];
            }
            if (RELU) {
                o0 = fmaxf(o0, 0.f); o1 = fmaxf(o1, 0.f);
                o2 = fmaxf(o2, 0.f); o3 = fmaxf(o3, 0.f);
            }
            float4 o = make_float4(o0, o1, o2, o3);
            *(float4*)(Cmat + (size_t)grow * Nc + gcol) = o;
        }
    }
}

// ---------------- text vector: masked mean pool ----------------
__global__ void k_textvec(const int* __restrict__ sentence, const float* __restrict__ mask,
                          const float* __restrict__ we, float* __restrict__ TEXTV)
{
    int b = blockIdx.x;
    int t = threadIdx.x;   // 192
    float4 acc = make_float4(0.f, 0.f, 0.f, 0.f);
    float msum = 0.f;
    for (int l = 0; l < L_; l++) {
        float w = mask[b * L_ + l];
        msum += w;
        int s = sentence[b * L_ + l];
        float4 f = *(const float4*)(we + (size_t)s * EMB_ + t * 4);
        acc.x += w * f.x; acc.y += w * f.y; acc.z += w * f.z; acc.w += w * f.w;
    }
    float inv = 1.f / (msum + 1e-9f);
    acc.x *= inv; acc.y *= inv; acc.z *= inv; acc.w *= inv;
    *(float4*)(TEXTV + b * EMB_ + t * 4) = acc;
}

// ---------------- gather logic rows ----------------
__global__ void k_gather(const int* __restrict__ nodes, const float* __restrict__ ent,
                         float* __restrict__ ROWS)
{
    int r = blockIdx.x;           // 0..32767
    int t = threadIdx.x;          // 192
    int b = r >> 12;
    int rem = r & 4095;
    int n = KS_ + (rem >> 3);
    int m = rem & 7;
    int e = nodes[(b * N_ + n) * M_ + m];
    *(float4*)(ROWS + (size_t)r * EMB_ + t * 4) =
        *(const float4*)(ent + (size_t)e * EMB_ + t * 4);
}

// ---------------- masked sum pool over M (kg: gather, logic: from MLP out) ----------------
__global__ void k_pool(const int* __restrict__ nodes, const float* __restrict__ nmask,
                       const float* __restrict__ ent, const float* __restrict__ ROWS,
                       float* __restrict__ X)
{
    int bn = blockIdx.x;          // 0..8191
    int t = threadIdx.x;          // 192
    int b = bn >> 10, n = bn & 1023;
    float4 acc = make_float4(0.f, 0.f, 0.f, 0.f);
    if (n < KS_) {
#pragma unroll
        for (int m = 0; m < M_; m++) {
            float w = nmask[bn * M_ + m];
            int e = nodes[bn * M_ + m];
            float4 f = *(const float4*)(ent + (size_t)e * EMB_ + t * 4);
            acc.x += w * f.x; acc.y += w * f.y; acc.z += w * f.z; acc.w += w * f.w;
        }
    } else {
        int rbase = (b * KS_ + (n - KS_)) * M_;
#pragma unroll
        for (int m = 0; m < M_; m++) {
            float w = nmask[bn * M_ + m];
            float4 f = *(const float4*)(ROWS + (size_t)(rbase + m) * EMB_ + t * 4);
            acc.x += w * f.x; acc.y += w * f.y; acc.z += w * f.z; acc.w += w * f.w;
        }
    }
    *(float4*)(X + (size_t)bn * EMB_ + t * 4) = acc;
}

// ---------------- build concat [text; NE] rows ----------------
__global__ void k_cat(const float* __restrict__ TEXTV, const float* __restrict__ NE,
                      float* __restrict__ CAT)
{
    int v = blockIdx.x * blockDim.x + threadIdx.x;
    if (v >= B_ * NN_ * 192) return;
    int row = v / 192, c = v % 192;
    int b = row / NN_, i = row % NN_;
    const float* src = (i == 0) ? (TEXTV + b * EMB_)
                                : (NE + (size_t)(b * N_ + i - 1) * EMB_);
    *(float4*)(CAT + (size_t)row * EMB_ + c * 4) = *(const float4*)(src + c * 4);
}

// ---------------- tiny projection: out[t,d] = sum_j tab[t,j] * W[j,d], d<256 ----------------
__global__ void k_tinyproj(const float* __restrict__ tab, const float* __restrict__ W,
                           float* __restrict__ out, int Kd)
{
    int t = blockIdx.x;
    int d = threadIdx.x;  // 256
    float s = 0.f;
    for (int j = 0; j < Kd; j++) s += tab[t * Kd + j] * W[j * D_ + d];
    out[t * D_ + d] = s;
}

// ---------------- add node-type embedding projection ----------------
__global__ void k_addtype(const int* __restrict__ ntypes, const float* __restrict__ TP,
                          float* __restrict__ Hf)
{
    int idx = blockIdx.x * blockDim.x + threadIdx.x;
    if (idx >= B_ * NN_ * D_) return;
    int row = idx >> 8, d = idx & 255;
    int b = row / NN_, i = row % NN_;
    int tc = ntypes[b * NN_ + i];
    Hf[idx] += TP[tc * D_ + d];
}

// ---------------- zero per-layer accumulators ----------------
__global__ void k_zero(unsigned* __restrict__ MXE, float* __restrict__ DEN,
                       float* __restrict__ AGG)
{
    int idx = blockIdx.x * blockDim.x + threadIdx.x;
    if (idx < B_ * NN_ * D_) AGG[idx] = 0.f;
    if (idx < B_ * NN_ * 4) { MXE[idx] = 0u; DEN[idx] = 0.f; }
}

// ---------------- edge logits + segment max ----------------
__global__ void k_logits(const float* __restrict__ Q, const float* __restrict__ Kt,
                         const int* __restrict__ edges, const int* __restrict__ etypes,
                         const float* __restrict__ KETl, float* __restrict__ LBUF,
                         unsigned* __restrict__ MXE)
{
    int gw = (blockIdx.x * blockDim.x + threadIdx.x) >> 5;
    int lane = threadIdx.x & 31;
    if (gw >= B_ * E_) return;
    int b = gw / E_, e = gw % E_;
    int src = edges[(b * 2) * E_ + e];
    int dst = edges[(b * 2 + 1) * E_ + e];
    int et = etypes[b * E_ + e];
    const float* q  = Q  + (size_t)(b * NN_ + dst) * D_;
    const float* kk = Kt + (size_t)(b * NN_ + src) * D_;
    const float* ke = KETl + et * D_;
    float p[4] = {0.f, 0.f, 0.f, 0.f};
#pragma unroll
    for (int s = 0; s < 8; s++) {
        int j = lane + 32 * s;
        p[s >> 1] += q[j] * (kk[j] + ke[j]);
    }
#pragma unroll
    for (int o = 16; o; o >>= 1) {
#pragma unroll
        for (int h = 0; h < 4; h++) p[h] += __shfl_xor_sync(~0u, p[h], o);
    }
    if (lane < 4) {
        float lg = p[lane] * 0.125f;   // 1/sqrt(64)
        LBUF[(size_t)gw * 4 + lane] = lg;
        atomicMax(&MXE[(b * NN_ + dst) * 4 + lane], fenc(lg));
    }
}

// ---------------- exp + segment sum ----------------
__global__ void k_exp(const int* __restrict__ edges, float* __restrict__ LBUF,
                      const unsigned* __restrict__ MXE, float* __restrict__ DEN)
{
    int idx = blockIdx.x * blockDim.x + threadIdx.x;
    if (idx >= B_ * E_ * 4) return;
    int h = idx & 3;
    int ge = idx >> 2;
    int b = ge / E_, e = ge % E_;
    int dst = edges[(b * 2 + 1) * E_ + e];
    float mx = fdec(MXE[(b * NN_ + dst) * 4 + h]);
    float ex = expf(LBUF[idx] - mx);
    LBUF[idx] = ex;
    atomicAdd(&DEN[(b * NN_ + dst) * 4 + h], ex);
}

// ---------------- weighted aggregate ----------------
__global__ void k_agg(const float* __restrict__ V, const int* __restrict__ edges,
                      const float* __restrict__ LBUF, const float* __restrict__ DEN,
                      float* __restrict__ AGG)
{
    int gw = (blockIdx.x * blockDim.x + threadIdx.x) >> 5;
    int lane = threadIdx.x & 31;
    if (gw >= B_ * E_) return;
    int b = gw / E_, e = gw % E_;
    int src = edges[(b * 2) * E_ + e];
    int dst = edges[(b * 2 + 1) * E_ + e];
    float alpha[4];
#pragma unroll
    for (int h = 0; h < 4; h++)
        alpha[h] = LBUF[(size_t)gw * 4 + h] / (DEN[(b * NN_ + dst) * 4 + h] + 1e-9f);
    const float* v = V + (size_t)(b * NN_ + src) * D_;
    float* agg = AGG + (size_t)(b * NN_ + dst) * D_;
#pragma unroll
    for (int s = 0; s < 8; s++) {
        int j = lane + 32 * s;
        atomicAdd(&agg[j], alpha[s >> 1] * v[j]);
    }
}

// ---------------- h = relu(h + agg) ----------------
__global__ void k_hupdate(float* __restrict__ Hf, const float* __restrict__ AGG)
{
    int idx = blockIdx.x * blockDim.x + threadIdx.x;
    if (idx >= B_ * NN_ * D_) return;
    Hf[idx] = fmaxf(Hf[idx] + AGG[idx], 0.f);
}

// ---------------- fold cls_w @ cls2_w into W2C, bias into B2 ----------------
__global__ void k_w2c(const float* __restrict__ cls_w, const float* __restrict__ cls_b,
                      const float* __restrict__ cls2_w, const float* __restrict__ cls2_b,
                      float* __restrict__ W2C, float* __restrict__ B2)
{
    int c = blockIdx.x;
    int tid = threadIdx.x;  // 256
    __shared__ __align__(16) float s2[EMB_];
    for (int e = tid; e < EMB_; e += 256) s2[e] = cls2_w[c * EMB_ + e];
    __syncthreads();
    for (int j = tid; j < 1280; j += 256) {
        const float* w = cls_w + (size_t)j * EMB_;
        float s = 0.f;
        for (int e4 = 0; e4 < EMB_ / 4; e4++) {
            float4 a = *(const float4*)(w + e4 * 4);
            float4 b = *(const float4*)(&s2[e4 * 4]);
            s += a.x * b.x + a.y * b.y + a.z * b.z + a.w * b.w;
        }
        W2C[c * 1280 + j] = s;
    }
    float p = 0.f;
    for (int e = tid; e < EMB_; e += 256) p += cls_b[e] * s2[e];
    __shared__ float red[256];
    red[tid] = p; __syncthreads();
    for (int s = 128; s; s >>= 1) { if (tid < s) red[tid] += red[tid + s]; __syncthreads(); }
    if (tid == 0) B2[c] = red[0] + cls2_b[c];
}

// ---------------- final output ----------------
__global__ void k_out(const float* __restrict__ Hf, const float* __restrict__ TEXTV,
                      const float* __restrict__ W2C, const float* __restrict__ B2,
                      float* __restrict__ out)
{
    int o = blockIdx.x;   // 400
    int b = o / C_, c = o % C_;
    int lane = threadIdx.x;  // 32
    const float* ctx = Hf + (size_t)(b * NN_) * D_;
    const float* lab = Hf + (size_t)(b * NN_ + 1 + c) * D_;
    const float* txt = TEXTV + b * EMB_;
    const float* w = W2C + c * 1280;
    float s = 0.f;
    for (int j = lane; j < 256; j += 32) s += ctx[j] * w[j];
    for (int j = lane; j < 256; j += 32) s += lab[j] * w[256 + j];
    for (int j = lane; j < 768; j += 32) s += txt[j] * w[512 + j];
#pragma unroll
    for (int off = 16; off; off >>= 1) s += __shfl_xor_sync(~0u, s, off);
    if (lane == 0) out[b * C_ + c] = s + B2[c];
}

// ---------------- host launch ----------------
static float* fsym(const void* s) { void* p = nullptr; cudaGetSymbolAddress(&p, s); return (float*)p; }

extern "C" void kernel_launch(void* const* d_in, const int* in_sizes, int n_in,
                              void* d_out, int out_size)
{
    const int*   sentence      = (const int*)  d_in[0];
    const float* mask          = (const float*)d_in[1];
    const int*   nodes         = (const int*)  d_in[2];
    const float* node_mask     = (const float*)d_in[3];
    const int*   node_types    = (const int*)  d_in[4];
    const int*   edges         = (const int*)  d_in[5];
    const int*   edge_types    = (const int*)  d_in[6];
    const float* word_embed    = (const float*)d_in[7];
    const float* entity_table  = (const float*)d_in[8];
    const float* type_table    = (const float*)d_in[9];
    const float* mlp_w1        = (const float*)d_in[10];
    const float* mlp_b1        = (const float*)d_in[11];
    const float* mlp_w2        = (const float*)d_in[12];
    const float* mlp_b2        = (const float*)d_in[13];
    const float* ntw_w         = (const float*)d_in[14];
    const float* proj_w        = (const float*)d_in[15];
    const float* proj_b        = (const float*)d_in[16];
    const float* type_proj_w   = (const float*)d_in[17];
    const float* edge_type_tab = (const float*)d_in[18];
    const float* gnn_wq        = (const float*)d_in[19];
    const float* gnn_wk        = (const float*)d_in[20];
    const float* gnn_wv        = (const float*)d_in[21];
    const float* gnn_we        = (const float*)d_in[22];
    const float* cls_w         = (const float*)d_in[23];
    const float* cls_b         = (const float*)d_in[24];
    const float* cls2_w        = (const float*)d_in[25];
    const float* cls2_b        = (const float*)d_in[26];
    float* out = (float*)d_out;

    float*    TEXTV = fsym(g_text);
    float*    ROWS  = fsym(g_rows);
    float*    HID   = fsym(g_hid);
    float*    X     = fsym(g_X);
    float*    NE    = fsym(g_NE);
    float*    CAT   = fsym(g_CAT);
    float*    Hf    = fsym(g_H);
    float*    Q     = fsym(g_Q);
    float*    Kb    = fsym(g_Kb);
    float*    V     = fsym(g_V);
    float*    TP    = fsym(g_TP);
    float*    KET   = fsym(g_KET);
    float*    LBUF  = fsym(g_LBUF);
    unsigned* MXE   = (unsigned*)fsym(g_MXE);
    float*    DEN   = fsym(g_DEN);
    float*    AGG   = fsym(g_AGG);
    float*    W2C   = fsym(g_W2C);
    float*    B2    = fsym(g_B2);

    // 1) text vector
    k_textvec<<<B_, 192>>>(sentence, mask, word_embed, TEXTV);

    // 2) gather logic rows, MLP (two big GEMMs)
    k_gather<<<NLROWS, 192>>>(nodes, entity_table, ROWS);
    sgemm128<true,  true><<<dim3(1024 / 128, NLROWS / 128), 256>>>(ROWS, mlp_w1, mlp_b1, HID, NLROWS, 1024, EMB_);
    sgemm128<false, true><<<dim3(EMB_ / 128, NLROWS / 128), 256>>>(HID, mlp_w2, mlp_b2, ROWS, NLROWS, EMB_, 1024);

    // 3) masked pool over M, then ntw_w GEMM (pool commuted before linear map)
    k_pool<<<B_ * N_, 192>>>(nodes, node_mask, entity_table, ROWS, X);
    sgemm128<false, false><<<dim3(EMB_ / 128, (B_ * N_) / 128), 256>>>(X, ntw_w, nullptr, NE, B_ * N_, EMB_, EMB_);

    // 4) concat + projection + type injection
    k_cat<<<(B_ * NN_ * 192 + 255) / 256, 256>>>(TEXTV, NE, CAT);
    k_tinyproj<<<100, 256>>>(type_table, type_proj_w, TP, TD_);
    k_tinyproj<<<TD_, 256>>>(edge_type_tab, gnn_we, KET, TD_);
    k_tinyproj<<<TD_, 256>>>(edge_type_tab, gnn_we + TD_ * D_, KET + TD_ * D_, TD_);
    sgemm128<false, true><<<dim3(D_ / 128, (B_ * NN_ + 127) / 128), 256>>>(CAT, proj_w, proj_b, Hf, B_ * NN_, D_, EMB_);
    k_addtype<<<(B_ * NN_ * D_ + 255) / 256, 256>>>(node_types, TP, Hf);

    // 5) GNN layers
    for (int l = 0; l < 2; l++) {
        const float* wq = gnn_wq + (size_t)l * D_ * D_;
        const float* wk = gnn_wk + (size_t)l * D_ * D_;
        const float* wv = gnn_wv + (size_t)l * D_ * D_;
        dim3 g(D_ / 128, (B_ * NN_ + 127) / 128);
        sgemm128<false, false><<<g, 256>>>(Hf, wq, nullptr, Q,  B_ * NN_, D_, D_);
        sgemm128<false, false><<<g, 256>>>(Hf, wk, nullptr, Kb, B_ * NN_, D_, D_);
        sgemm128<false, false><<<g, 256>>>(Hf, wv, nullptr, V,  B_ * NN_, D_, D_);
        k_zero<<<(B_ * NN_ * D_ + 255) / 256, 256>>>(MXE, DEN, AGG);
        k_logits<<<(B_ * E_ * 32) / 256, 256>>>(Q, Kb, edges, edge_types, KET + l * TD_ * D_, LBUF, MXE);
        k_exp<<<(B_ * E_ * 4 + 255) / 256, 256>>>(edges, LBUF, MXE, DEN);
        k_agg<<<(B_ * E_ * 32) / 256, 256>>>(V, edges, LBUF, DEN, AGG);
        k_hupdate<<<(B_ * NN_ * D_ + 255) / 256, 256>>>(Hf, AGG);
    }

    // 6) fold classifier + final dot products
    k_w2c<<<C_, 256>>>(cls_w, cls_b, cls2_w, cls2_b, W2C, B2);
    k_out<<<B_ * C_, 32>>>(Hf, TEXTV, W2C, B2, out);
}

// round 2
// speedup vs baseline: 1.1896x; 1.1896x over previous
#include <cuda_runtime.h>
#include <math.h>

// ---------------- problem dims ----------------
#define B_   8
#define L_   256
#define N_   1024
#define M_   8
#define E_   16384
#define C_   50
#define EMB_ 768
#define D_   256
#define TD_  50
#define NN_  1025           // N+1
#define KS_  512            // K_SPLIT
#define NLROWS 32768        // B*KS*M logic rows

// ---------------- device scratch ----------------
__device__ float    g_text[B_ * EMB_];
__device__ float    g_rows[NLROWS * EMB_];       // MLP output rows
__device__ float    g_hid[NLROWS * 1024];
__device__ int      g_idx[NLROWS];
__device__ float    g_X[B_ * N_ * EMB_];         // pooled pre-ntw
__device__ float    g_NE[B_ * N_ * EMB_];
__device__ float    g_CAT[B_ * NN_ * EMB_];
__device__ float    g_H[B_ * NN_ * D_];
__device__ float    g_Q[B_ * NN_ * D_];
__device__ float    g_Kb[B_ * NN_ * D_];
__device__ float    g_V[B_ * NN_ * D_];
__device__ float    g_TP[100 * D_];
__device__ float    g_KET[2 * TD_ * D_];
__device__ float    g_LBUF[B_ * E_ * 4];
__device__ unsigned g_MXE[B_ * NN_ * 4];
__device__ float    g_DEN[B_ * NN_ * 4];
__device__ float    g_AGG[B_ * NN_ * D_];
__device__ float    g_W2C[C_ * 1280];
__device__ float    g_B2[C_];

// ---------------- helpers ----------------
__device__ __forceinline__ unsigned fenc(float f) {
    unsigned u = __float_as_uint(f);
    return (u & 0x80000000u) ? ~u : (u | 0x80000000u);
}
__device__ __forceinline__ float fdec(unsigned u) {
    unsigned v = (u & 0x80000000u) ? (u & 0x7fffffffu) : ~u;
    return __uint_as_float(v);
}
__device__ __forceinline__ float to_tf32(float f) {
    unsigned u;
    asm("cvt.rna.tf32.f32 %0, %1;" : "=r"(u) : "f"(f));
    return __uint_as_float(u);
}
__device__ __forceinline__ void mma_tf32(float* d, const float* a2, const float* b2) {
    asm volatile(
        "mma.sync.aligned.m16n8k8.row.col.f32.tf32.tf32.f32 "
        "{%0,%1,%2,%3}, {%4,%5,%6,%7}, {%8,%9}, {%0,%1,%2,%3};\n"
        : "+f"(d[0]), "+f"(d[1]), "+f"(d[2]), "+f"(d[3])
        : "r"(__float_as_uint(a2[0])), "r"(__float_as_uint(a2[1])),
          "r"(__float_as_uint(a2[2])), "r"(__float_as_uint(a2[3])),
          "r"(__float_as_uint(b2[0])), "r"(__float_as_uint(b2[1])));
}

// ---------------- TF32 tensor-core GEMM ----------------
// C[M,N] = A[M,K] @ B[K,N] (+bias)(relu). K % 32 == 0, N % 128 == 0.
// Optional aidx: A row r is read from A[aidx[r]] (fused gather).
// Block tile 128x128x32, 256 threads (8 warps as 2m x 4n), warp tile 64x32.
// smem layout interleaves k within groups of 8: kint = (k&~7) + (k%4)*2 + ((k/4)&1),
// so mma fragment pairs (k, k+4) are adjacent -> ld.shared.v2.
#define PADK 36
template<bool RELU, bool BIAS>
__global__ __launch_bounds__(256) void gemm_tf32(
    const float* __restrict__ A, const float* __restrict__ Bm,
    const float* __restrict__ bias, float* __restrict__ Cmat,
    int Mr, int Nc, int Kd, const int* __restrict__ aidx)
{
    __shared__ __align__(16) float As[128 * PADK];
    __shared__ __align__(16) float Bs[128 * PADK];

    const int tid  = threadIdx.x;
    const int wid  = tid >> 5;
    const int lane = tid & 31;
    const int gid  = lane >> 2;     // groupID
    const int tig  = lane & 3;      // thread in group
    const int warpM = (wid >> 2) * 64;
    const int warpN = (wid & 3) * 32;
    const int rowBase = blockIdx.y * 128;
    const int colBase = blockIdx.x * 128;

    float acc[4][4][4];
#pragma unroll
    for (int i = 0; i < 4; i++)
#pragma unroll
        for (int j = 0; j < 4; j++)
#pragma unroll
            for (int q = 0; q < 4; q++) acc[i][j][q] = 0.f;

    // per-thread load coords
    const int ar = (tid * 4) >> 5;          // base pattern; computed per i below
    (void)ar;

    float4 pa[4], pb[4];

    // ---- load tile k0 into regs ----
    auto load_regs = [&](int k0) {
#pragma unroll
        for (int i = 0; i < 4; i++) {
            int v = tid + i * 256;          // 0..1023
            int r = v >> 3, kq = v & 7;
            int grow = rowBase + r;
            float4 f = make_float4(0.f, 0.f, 0.f, 0.f);
            if (grow < Mr) {
                int arow = aidx ? aidx[grow] : grow;
                f = *(const float4*)(A + (size_t)arow * Kd + k0 + kq * 4);
            }
            pa[i] = f;
        }
#pragma unroll
        for (int i = 0; i < 4; i++) {
            int v = tid + i * 256;
            int kk = v >> 5, nq = v & 31;
            pb[i] = *(const float4*)(Bm + (size_t)(k0 + kk) * Nc + colBase + nq * 4);
        }
    };
    auto store_smem = [&]() {
#pragma unroll
        for (int i = 0; i < 4; i++) {
            int v = tid + i * 256;
            int r = v >> 3, kq = v & 7;
            int g8 = (kq >> 1) * 8, off = kq & 1;
            float* dst = As + r * PADK + g8 + off;
            dst[0] = to_tf32(pa[i].x);
            dst[2] = to_tf32(pa[i].y);
            dst[4] = to_tf32(pa[i].z);
            dst[6] = to_tf32(pa[i].w);
        }
#pragma unroll
        for (int i = 0; i < 4; i++) {
            int v = tid + i * 256;
            int kk = v >> 5, nq = v & 31;
            int kint = (kk & ~7) + ((kk & 3) << 1) + ((kk >> 2) & 1);
            Bs[(nq * 4 + 0) * PADK + kint] = to_tf32(pb[i].x);
            Bs[(nq * 4 + 1) * PADK + kint] = to_tf32(pb[i].y);
            Bs[(nq * 4 + 2) * PADK + kint] = to_tf32(pb[i].z);
            Bs[(nq * 4 + 3) * PADK + kint] = to_tf32(pb[i].w);
        }
    };

    load_regs(0);
    store_smem();
    __syncthreads();

    for (int k0 = 0; k0 < Kd; k0 += 32) {
        bool more = (k0 + 32) < Kd;
        if (more) load_regs(k0 + 32);

#pragma unroll
        for (int ks = 0; ks < 4; ks++) {
            float af[4][4];   // [mt][a0,a1,a2,a3]
            float bf[4][2];
#pragma unroll
            for (int mt = 0; mt < 4; mt++) {
                int r0 = warpM + mt * 16 + gid;
                float2 x = *(const float2*)(As + r0 * PADK + ks * 8 + tig * 2);
                float2 y = *(const float2*)(As + (r0 + 8) * PADK + ks * 8 + tig * 2);
                af[mt][0] = x.x; af[mt][2] = x.y;
                af[mt][1] = y.x; af[mt][3] = y.y;
            }
#pragma unroll
            for (int nt = 0; nt < 4; nt++) {
                int c0 = warpN + nt * 8 + gid;
                float2 z = *(const float2*)(Bs + c0 * PADK + ks * 8 + tig * 2);
                bf[nt][0] = z.x; bf[nt][1] = z.y;
            }
#pragma unroll
            for (int mt = 0; mt < 4; mt++)
#pragma unroll
                for (int nt = 0; nt < 4; nt++)
                    mma_tf32(acc[mt][nt], af[mt], bf[nt]);
        }

        __syncthreads();
        if (more) {
            store_smem();
            __syncthreads();
        }
    }

    // ---- epilogue ----
#pragma unroll
    for (int mt = 0; mt < 4; mt++) {
        int r0 = rowBase + warpM + mt * 16 + gid;
#pragma unroll
        for (int nt = 0; nt < 4; nt++) {
            int c0 = colBase + warpN + nt * 8 + tig * 2;
            float b0 = 0.f, b1 = 0.f;
            if (BIAS) { b0 = bias[c0]; b1 = bias[c0 + 1]; }
            float o0 = acc[mt][nt][0] + b0, o1 = acc[mt][nt][1] + b1;
            float o2 = acc[mt][nt][2] + b0, o3 = acc[mt][nt][3] + b1;
            if (RELU) {
                o0 = fmaxf(o0, 0.f); o1 = fmaxf(o1, 0.f);
                o2 = fmaxf(o2, 0.f); o3 = fmaxf(o3, 0.f);
            }
            if (r0 < Mr)     *(float2*)(Cmat + (size_t)r0 * Nc + c0)       = make_float2(o0, o1);
            if (r0 + 8 < Mr) *(float2*)(Cmat + (size_t)(r0 + 8) * Nc + c0) = make_float2(o2, o3);
        }
    }
}

// ---------------- text vector: masked mean pool ----------------
__global__ void k_textvec(const int* __restrict__ sentence, const float* __restrict__ mask,
                          const float* __restrict__ we, float* __restrict__ TEXTV)
{
    int b = blockIdx.x;
    int t = threadIdx.x;   // 192
    float4 acc = make_float4(0.f, 0.f, 0.f, 0.f);
    float msum = 0.f;
    for (int l = 0; l < L_; l++) {
        float w = mask[b * L_ + l];
        msum += w;
        int s = sentence[b * L_ + l];
        float4 f = *(const float4*)(we + (size_t)s * EMB_ + t * 4);
        acc.x += w * f.x; acc.y += w * f.y; acc.z += w * f.z; acc.w += w * f.w;
    }
    float inv = 1.f / (msum + 1e-9f);
    acc.x *= inv; acc.y *= inv; acc.z *= inv; acc.w *= inv;
    *(float4*)(TEXTV + b * EMB_ + t * 4) = acc;
}

// ---------------- build fused-gather row index ----------------
__global__ void k_buildidx(const int* __restrict__ nodes, int* __restrict__ IDX)
{
    int r = blockIdx.x * blockDim.x + threadIdx.x;
    if (r >= NLROWS) return;
    int b = r >> 12;
    int rem = r & 4095;
    int n = KS_ + (rem >> 3);
    int m = rem & 7;
    IDX[r] = nodes[(b * N_ + n) * M_ + m];
}

// ---------------- masked sum pool over M ----------------
__global__ void k_pool(const int* __restrict__ nodes, const float* __restrict__ nmask,
                       const float* __restrict__ ent, const float* __restrict__ ROWS,
                       float* __restrict__ X)
{
    int bn = blockIdx.x;          // 0..8191
    int t = threadIdx.x;          // 192
    int b = bn >> 10, n = bn & 1023;
    float4 acc = make_float4(0.f, 0.f, 0.f, 0.f);
    if (n < KS_) {
#pragma unroll
        for (int m = 0; m < M_; m++) {
            float w = nmask[bn * M_ + m];
            int e = nodes[bn * M_ + m];
            float4 f = *(const float4*)(ent + (size_t)e * EMB_ + t * 4);
            acc.x += w * f.x; acc.y += w * f.y; acc.z += w * f.z; acc.w += w * f.w;
        }
    } else {
        int rbase = (b * KS_ + (n - KS_)) * M_;
#pragma unroll
        for (int m = 0; m < M_; m++) {
            float w = nmask[bn * M_ + m];
            float4 f = *(const float4*)(ROWS + (size_t)(rbase + m) * EMB_ + t * 4);
            acc.x += w * f.x; acc.y += w * f.y; acc.z += w * f.z; acc.w += w * f.w;
        }
    }
    *(float4*)(X + (size_t)bn * EMB_ + t * 4) = acc;
}

// ---------------- build concat [text; NE] rows ----------------
__global__ void k_cat(const float* __restrict__ TEXTV, const float* __restrict__ NE,
                      float* __restrict__ CAT)
{
    int v = blockIdx.x * blockDim.x + threadIdx.x;
    if (v >= B_ * NN_ * 192) return;
    int row = v / 192, c = v % 192;
    int b = row / NN_, i = row % NN_;
    const float* src = (i == 0) ? (TEXTV + b * EMB_)
                                : (NE + (size_t)(b * N_ + i - 1) * EMB_);
    *(float4*)(CAT + (size_t)row * EMB_ + c * 4) = *(const float4*)(src + c * 4);
}

// ---------------- tiny projection ----------------
__global__ void k_tinyproj(const float* __restrict__ tab, const float* __restrict__ W,
                           float* __restrict__ out, int Kd)
{
    int t = blockIdx.x;
    int d = threadIdx.x;  // 256
    float s = 0.f;
    for (int j = 0; j < Kd; j++) s += tab[t * Kd + j] * W[j * D_ + d];
    out[t * D_ + d] = s;
}

// ---------------- add node-type embedding projection ----------------
__global__ void k_addtype(const int* __restrict__ ntypes, const float* __restrict__ TP,
                          float* __restrict__ Hf)
{
    int idx = blockIdx.x * blockDim.x + threadIdx.x;
    if (idx >= B_ * NN_ * D_) return;
    int row = idx >> 8, d = idx & 255;
    int b = row / NN_, i = row % NN_;
    int tc = ntypes[b * NN_ + i];
    Hf[idx] += TP[tc * D_ + d];
}

// ---------------- zero per-layer accumulators ----------------
__global__ void k_zero(unsigned* __restrict__ MXE, float* __restrict__ DEN,
                       float* __restrict__ AGG)
{
    int idx = blockIdx.x * blockDim.x + threadIdx.x;
    if (idx < B_ * NN_ * D_) AGG[idx] = 0.f;
    if (idx < B_ * NN_ * 4) { MXE[idx] = 0u; DEN[idx] = 0.f; }
}

// ---------------- edge logits + segment max ----------------
__global__ void k_logits(const float* __restrict__ Q, const float* __restrict__ Kt,
                         const int* __restrict__ edges, const int* __restrict__ etypes,
                         const float* __restrict__ KETl, float* __restrict__ LBUF,
                         unsigned* __restrict__ MXE)
{
    int gw = (blockIdx.x * blockDim.x + threadIdx.x) >> 5;
    int lane = threadIdx.x & 31;
    if (gw >= B_ * E_) return;
    int b = gw / E_, e = gw % E_;
    int src = edges[(b * 2) * E_ + e];
    int dst = edges[(b * 2 + 1) * E_ + e];
    int et = etypes[b * E_ + e];
    const float* q  = Q  + (size_t)(b * NN_ + dst) * D_;
    const float* kk = Kt + (size_t)(b * NN_ + src) * D_;
    const float* ke = KETl + et * D_;
    float p[4] = {0.f, 0.f, 0.f, 0.f};
#pragma unroll
    for (int s = 0; s < 8; s++) {
        int j = lane + 32 * s;
        p[s >> 1] += q[j] * (kk[j] + ke[j]);
    }
#pragma unroll
    for (int o = 16; o; o >>= 1) {
#pragma unroll
        for (int h = 0; h < 4; h++) p[h] += __shfl_xor_sync(~0u, p[h], o);
    }
    if (lane < 4) {
        float lg = p[lane] * 0.125f;   // 1/sqrt(64)
        LBUF[(size_t)gw * 4 + lane] = lg;
        atomicMax(&MXE[(b * NN_ + dst) * 4 + lane], fenc(lg));
    }
}

// ---------------- exp + segment sum ----------------
__global__ void k_exp(const int* __restrict__ edges, float* __restrict__ LBUF,
                      const unsigned* __restrict__ MXE, float* __restrict__ DEN)
{
    int idx = blockIdx.x * blockDim.x + threadIdx.x;
    if (idx >= B_ * E_ * 4) return;
    int h = idx & 3;
    int ge = idx >> 2;
    int b = ge / E_, e = ge % E_;
    int dst = edges[(b * 2 + 1) * E_ + e];
    float mx = fdec(MXE[(b * NN_ + dst) * 4 + h]);
    float ex = expf(LBUF[idx] - mx);
    LBUF[idx] = ex;
    atomicAdd(&DEN[(b * NN_ + dst) * 4 + h], ex);
}

// ---------------- weighted aggregate ----------------
__global__ void k_agg(const float* __restrict__ V, const int* __restrict__ edges,
                      const float* __restrict__ LBUF, const float* __restrict__ DEN,
                      float* __restrict__ AGG)
{
    int gw = (blockIdx.x * blockDim.x + threadIdx.x) >> 5;
    int lane = threadIdx.x & 31;
    if (gw >= B_ * E_) return;
    int b = gw / E_, e = gw % E_;
    int src = edges[(b * 2) * E_ + e];
    int dst = edges[(b * 2 + 1) * E_ + e];
    float alpha[4];
#pragma unroll
    for (int h = 0; h < 4; h++)
        alpha[h] = LBUF[(size_t)gw * 4 + h] / (DEN[(b * NN_ + dst) * 4 + h] + 1e-9f);
    const float* v = V + (size_t)(b * NN_ + src) * D_;
    float* agg = AGG + (size_t)(b * NN_ + dst) * D_;
#pragma unroll
    for (int s = 0; s < 8; s++) {
        int j = lane + 32 * s;
        atomicAdd(&agg[j], alpha[s >> 1] * v[j]);
    }
}

// ---------------- h = relu(h + agg) ----------------
__global__ void k_hupdate(float* __restrict__ Hf, const float* __restrict__ AGG)
{
    int idx = blockIdx.x * blockDim.x + threadIdx.x;
    if (idx >= B_ * NN_ * D_) return;
    Hf[idx] = fmaxf(Hf[idx] + AGG[idx], 0.f);
}

// ---------------- fold cls_w @ cls2_w into W2C, bias into B2 ----------------
__global__ void k_w2c(const float* __restrict__ cls_w, const float* __restrict__ cls_b,
                      const float* __restrict__ cls2_w, const float* __restrict__ cls2_b,
                      float* __restrict__ W2C, float* __restrict__ B2)
{
    int c = blockIdx.x;
    int tid = threadIdx.x;  // 256
    __shared__ __align__(16) float s2[EMB_];
    for (int e = tid; e < EMB_; e += 256) s2[e] = cls2_w[c * EMB_ + e];
    __syncthreads();
    for (int j = tid; j < 1280; j += 256) {
        const float* w = cls_w + (size_t)j * EMB_;
        float s = 0.f;
        for (int e4 = 0; e4 < EMB_ / 4; e4++) {
            float4 a = *(const float4*)(w + e4 * 4);
            float4 b = *(const float4*)(&s2[e4 * 4]);
            s += a.x * b.x + a.y * b.y + a.z * b.z + a.w * b.w;
        }
        W2C[c * 1280 + j] = s;
    }
    float p = 0.f;
    for (int e = tid; e < EMB_; e += 256) p += cls_b[e] * s2[e];
    __shared__ float red[256];
    red[tid] = p; __syncthreads();
    for (int s = 128; s; s >>= 1) { if (tid < s) red[tid] += red[tid + s]; __syncthreads(); }
    if (tid == 0) B2[c] = red[0] + cls2_b[c];
}

// ---------------- final output ----------------
__global__ void k_out(const float* __restrict__ Hf, const float* __restrict__ TEXTV,
                      const float* __restrict__ W2C, const float* __restrict__ B2,
                      float* __restrict__ out)
{
    int o = blockIdx.x;   // 400
    int b = o / C_, c = o % C_;
    int lane = threadIdx.x;  // 32
    const float* ctx = Hf + (size_t)(b * NN_) * D_;
    const float* lab = Hf + (size_t)(b * NN_ + 1 + c) * D_;
    const float* txt = TEXTV + b * EMB_;
    const float* w = W2C + c * 1280;
    float s = 0.f;
    for (int j = lane; j < 256; j += 32) s += ctx[j] * w[j];
    for (int j = lane; j < 256; j += 32) s += lab[j] * w[256 + j];
    for (int j = lane; j < 768; j += 32) s += txt[j] * w[512 + j];
#pragma unroll
    for (int off = 16; off; off >>= 1) s += __shfl_xor_sync(~0u, s, off);
    if (lane == 0) out[b * C_ + c] = s + B2[c];
}

// ---------------- host launch ----------------
static float* fsym(const void* s) { void* p = nullptr; cudaGetSymbolAddress(&p, s); return (float*)p; }

extern "C" void kernel_launch(void* const* d_in, const int* in_sizes, int n_in,
                              void* d_out, int out_size)
{
    const int*   sentence      = (const int*)  d_in[0];
    const float* mask          = (const float*)d_in[1];
    const int*   nodes         = (const int*)  d_in[2];
    const float* node_mask     = (const float*)d_in[3];
    const int*   node_types    = (const int*)  d_in[4];
    const int*   edges         = (const int*)  d_in[5];
    const int*   edge_types    = (const int*)  d_in[6];
    const float* word_embed    = (const float*)d_in[7];
    const float* entity_table  = (const float*)d_in[8];
    const float* type_table    = (const float*)d_in[9];
    const float* mlp_w1        = (const float*)d_in[10];
    const float* mlp_b1        = (const float*)d_in[11];
    const float* mlp_w2        = (const float*)d_in[12];
    const float* mlp_b2        = (const float*)d_in[13];
    const float* ntw_w         = (const float*)d_in[14];
    const float* proj_w        = (const float*)d_in[15];
    const float* proj_b        = (const float*)d_in[16];
    const float* type_proj_w   = (const float*)d_in[17];
    const float* edge_type_tab = (const float*)d_in[18];
    const float* gnn_wq        = (const float*)d_in[19];
    const float* gnn_wk        = (const float*)d_in[20];
    const float* gnn_wv        = (const float*)d_in[21];
    const float* gnn_we        = (const float*)d_in[22];
    const float* cls_w         = (const float*)d_in[23];
    const float* cls_b         = (const float*)d_in[24];
    const float* cls2_w        = (const float*)d_in[25];
    const float* cls2_b        = (const float*)d_in[26];
    float* out = (float*)d_out;

    float*    TEXTV = fsym(g_text);
    float*    ROWS  = fsym(g_rows);
    float*    HID   = fsym(g_hid);
    int*      IDX   = (int*)fsym(g_idx);
    float*    X     = fsym(g_X);
    float*    NE    = fsym(g_NE);
    float*    CAT   = fsym(g_CAT);
    float*    Hf    = fsym(g_H);
    float*    Q     = fsym(g_Q);
    float*    Kb    = fsym(g_Kb);
    float*    V     = fsym(g_V);
    float*    TP    = fsym(g_TP);
    float*    KET   = fsym(g_KET);
    float*    LBUF  = fsym(g_LBUF);
    unsigned* MXE   = (unsigned*)fsym(g_MXE);
    float*    DEN   = fsym(g_DEN);
    float*    AGG   = fsym(g_AGG);
    float*    W2C   = fsym(g_W2C);
    float*    B2    = fsym(g_B2);

    // 1) text vector
    k_textvec<<<B_, 192>>>(sentence, mask, word_embed, TEXTV);

    // 2) MLP (two big TF32 GEMMs; gather fused into GEMM1 via row indices)
    k_buildidx<<<NLROWS / 256, 256>>>(nodes, IDX);
    gemm_tf32<true,  true><<<dim3(1024 / 128, NLROWS / 128), 256>>>(entity_table, mlp_w1, mlp_b1, HID, NLROWS, 1024, EMB_, IDX);
    gemm_tf32<false, true><<<dim3(EMB_ / 128, NLROWS / 128), 256>>>(HID, mlp_w2, mlp_b2, ROWS, NLROWS, EMB_, 1024, nullptr);

    // 3) masked pool over M, then ntw_w GEMM (pool commuted before linear map)
    k_pool<<<B_ * N_, 192>>>(nodes, node_mask, entity_table, ROWS, X);
    gemm_tf32<false, false><<<dim3(EMB_ / 128, (B_ * N_) / 128), 256>>>(X, ntw_w, nullptr, NE, B_ * N_, EMB_, EMB_, nullptr);

    // 4) concat + projection + type injection
    k_cat<<<(B_ * NN_ * 192 + 255) / 256, 256>>>(TEXTV, NE, CAT);
    k_tinyproj<<<100, 256>>>(type_table, type_proj_w, TP, TD_);
    k_tinyproj<<<TD_, 256>>>(edge_type_tab, gnn_we, KET, TD_);
    k_tinyproj<<<TD_, 256>>>(edge_type_tab, gnn_we + TD_ * D_, KET + TD_ * D_, TD_);
    gemm_tf32<false, true><<<dim3(D_ / 128, (B_ * NN_ + 127) / 128), 256>>>(CAT, proj_w, proj_b, Hf, B_ * NN_, D_, EMB_, nullptr);
    k_addtype<<<(B_ * NN_ * D_ + 255) / 256, 256>>>(node_types, TP, Hf);

    // 5) GNN layers
    for (int l = 0; l < 2; l++) {
        const float* wq = gnn_wq + (size_t)l * D_ * D_;
        const float* wk = gnn_wk + (size_t)l * D_ * D_;
        const float* wv = gnn_wv + (size_t)l * D_ * D_;
        dim3 g(D_ / 128, (B_ * NN_ + 127) / 128);
        gemm_tf32<false, false><<<g, 256>>>(Hf, wq, nullptr, Q,  B_ * NN_, D_, D_, nullptr);
        gemm_tf32<false, false><<<g, 256>>>(Hf, wk, nullptr, Kb, B_ * NN_, D_, D_, nullptr);
        gemm_tf32<false, false><<<g, 256>>>(Hf, wv, nullptr, V,  B_ * NN_, D_, D_, nullptr);
        k_zero<<<(B_ * NN_ * D_ + 255) / 256, 256>>>(MXE, DEN, AGG);
        k_logits<<<(B_ * E_ * 32) / 256, 256>>>(Q, Kb, edges, edge_types, KET + l * TD_ * D_, LBUF, MXE);
        k_exp<<<(B_ * E_ * 4 + 255) / 256, 256>>>(edges, LBUF, MXE, DEN);
        k_agg<<<(B_ * E_ * 32) / 256, 256>>>(V, edges, LBUF, DEN, AGG);
        k_hupdate<<<(B_ * NN_ * D_ + 255) / 256, 256>>>(Hf, AGG);
    }

    // 6) fold classifier + final dot products
    k_w2c<<<C_, 256>>>(cls_w, cls_b, cls2_w, cls2_b, W2C, B2);
    k_out<<<B_ * C_, 32>>>(Hf, TEXTV, W2C, B2, out);
}

// round 3
// speedup vs baseline: 2.1271x; 1.7881x over previous
#include <cuda_runtime.h>
#include <math.h>

// ---------------- problem dims ----------------
#define B_   8
#define L_   256
#define N_   1024
#define M_   8
#define E_   16384
#define C_   50
#define EMB_ 768
#define D_   256
#define TD_  50
#define NN_  1025           // N+1
#define KS_  512            // K_SPLIT
#define NLROWS 32768        // B*KS*M logic rows

// ---------------- device scratch ----------------
__device__ float    g_text[B_ * EMB_];
__device__ float    g_rows[NLROWS * EMB_];       // MLP output rows
__device__ float    g_hid[NLROWS * 1024];
__device__ int      g_idx[NLROWS];
__device__ float    g_X[B_ * N_ * EMB_];         // pooled pre-ntw
__device__ float    g_NE[B_ * N_ * EMB_];
__device__ float    g_CAT[B_ * NN_ * EMB_];
__device__ float    g_H[B_ * NN_ * D_];
__device__ float    g_QKV[B_ * NN_ * 768];
__device__ float    g_WQKV[2 * 256 * 768];
__device__ float    g_TP[100 * D_];
__device__ float    g_KET[2 * TD_ * D_];
__device__ float    g_LBUF[B_ * E_ * 4];
__device__ unsigned g_MXE[B_ * NN_ * 4];
__device__ float    g_DEN[B_ * NN_ * 4];
__device__ float    g_AGG[B_ * NN_ * D_];
__device__ float    g_W2C[C_ * 1280];
__device__ float    g_B2[C_];

// ---------------- helpers ----------------
__device__ __forceinline__ unsigned fenc(float f) {
    unsigned u = __float_as_uint(f);
    return (u & 0x80000000u) ? ~u : (u | 0x80000000u);
}
__device__ __forceinline__ float fdec(unsigned u) {
    unsigned v = (u & 0x80000000u) ? (u & 0x7fffffffu) : ~u;
    return __uint_as_float(v);
}
__device__ __forceinline__ float to_tf32(float f) {
    unsigned u;
    asm("cvt.rna.tf32.f32 %0, %1;" : "=r"(u) : "f"(f));
    return __uint_as_float(u);
}
__device__ __forceinline__ void mma_tf32(float* d, const float* a4, const float* b2) {
    asm volatile(
        "mma.sync.aligned.m16n8k8.row.col.f32.tf32.tf32.f32 "
        "{%0,%1,%2,%3}, {%4,%5,%6,%7}, {%8,%9}, {%0,%1,%2,%3};\n"
        : "+f"(d[0]), "+f"(d[1]), "+f"(d[2]), "+f"(d[3])
        : "r"(__float_as_uint(a4[0])), "r"(__float_as_uint(a4[1])),
          "r"(__float_as_uint(a4[2])), "r"(__float_as_uint(a4[3])),
          "r"(__float_as_uint(b2[0])), "r"(__float_as_uint(b2[1])));
}

// ---------------- TF32 tensor-core GEMM, fragment-native smem ----------------
// C[M,N] = A[M,K] @ B[K,N] (+bias)(relu). K%32==0, N%128==0.
// Block 128x128x32, 8 warps (2m x 4n), warp 64x32. Double buffered.
// A smem: segment (m16*4+ks), stride 132 floats; element (rr,kk) at
//   seg*132 + ((rr&7)*4 + (kk&3))*4 + (rr>>3) + 2*(kk>>2)   -> frag = 1x ld.v4 / thread
// B smem: segment (ks*16+n8), stride 66 floats; element (c,kk) at
//   seg*66 + ((c&7)*4 + (kk&3))*2 + (kk>>2)                 -> frag = 1x ld.v2 / thread
#define ASEG 132
#define BSEG 66
#define ABUF 4224      // 32 segs * 132
#define BBUF 4224      // 64 segs * 66
#define GSMEM ((ABUF + BBUF) * 2 * 4)

template<bool RELU, bool BIAS>
__global__ __launch_bounds__(256) void gemm_tf32(
    const float* __restrict__ A, const float* __restrict__ Bm,
    const float* __restrict__ bias, float* __restrict__ Cmat,
    int Mr, int Nc, int Kd, const int* __restrict__ aidx)
{
    extern __shared__ __align__(16) float S[];
    float* Abuf[2] = {S, S + ABUF};
    float* Bbuf[2] = {S + 2 * ABUF, S + 2 * ABUF + BBUF};

    const int tid  = threadIdx.x;
    const int wid  = tid >> 5;
    const int lane = tid & 31;
    const int m16b = (wid >> 2) * 4;   // warpM/16
    const int n8b  = (wid & 3) * 4;    // warpN/8
    const int rowBase = blockIdx.y * 128;
    const int colBase = blockIdx.x * 128;

    float acc[4][4][4];
#pragma unroll
    for (int i = 0; i < 4; i++)
#pragma unroll
        for (int j = 0; j < 4; j++)
#pragma unroll
            for (int q = 0; q < 4; q++) acc[i][j][q] = 0.f;

    float4 pa[4], pb[4];

    auto load_regs = [&](int k0) {
#pragma unroll
        for (int i = 0; i < 4; i++) {
            int v = tid + i * 256;          // 0..1023
            int r = v >> 3, kq = v & 7;
            int grow = rowBase + r;
            float4 f = make_float4(0.f, 0.f, 0.f, 0.f);
            if (grow < Mr) {
                int arow = aidx ? aidx[grow] : grow;
                f = *(const float4*)(A + (size_t)arow * Kd + k0 + kq * 4);
            }
            pa[i] = f;
        }
#pragma unroll
        for (int i = 0; i < 4; i++) {
            int v = tid + i * 256;
            int kk = v >> 5, nq = v & 31;
            pb[i] = *(const float4*)(Bm + (size_t)(k0 + kk) * Nc + colBase + nq * 4);
        }
    };
    auto store_smem = [&](int buf) {
        float* Asb = Abuf[buf];
        float* Bsb = Bbuf[buf];
#pragma unroll
        for (int i = 0; i < 4; i++) {
            int v = tid + i * 256;
            int r = v >> 3, kq = v & 7;
            int m16 = r >> 4, rr = r & 15;
            int ks = kq >> 1;
            float* p = Asb + (m16 * 4 + ks) * ASEG + (rr & 7) * 16
                     + (rr >> 3) + ((kq & 1) << 1);
            p[0]  = to_tf32(pa[i].x);
            p[4]  = to_tf32(pa[i].y);
            p[8]  = to_tf32(pa[i].z);
            p[12] = to_tf32(pa[i].w);
        }
#pragma unroll
        for (int i = 0; i < 4; i++) {
            int v = tid + i * 256;
            int kk = v >> 5, nq = v & 31;
            int ks = kk >> 3, kkk = kk & 7;
            int n8 = nq >> 1;
            float* p = Bsb + (ks * 16 + n8) * BSEG + (nq & 1) * 32
                     + ((kkk & 3) << 1) + (kkk >> 2);
            p[0]  = to_tf32(pb[i].x);
            p[8]  = to_tf32(pb[i].y);
            p[16] = to_tf32(pb[i].z);
            p[24] = to_tf32(pb[i].w);
        }
    };

    load_regs(0);
    store_smem(0);
    __syncthreads();

    int cur = 0;
    for (int k0 = 0; k0 < Kd; k0 += 32) {
        bool more = (k0 + 32) < Kd;
        if (more) load_regs(k0 + 32);

        const float* Asb = Abuf[cur];
        const float* Bsb = Bbuf[cur];
#pragma unroll
        for (int ks = 0; ks < 4; ks++) {
            float4 av[4];
            float2 bv[4];
#pragma unroll
            for (int mt = 0; mt < 4; mt++)
                av[mt] = *(const float4*)(Asb + ((m16b + mt) * 4 + ks) * ASEG + lane * 4);
#pragma unroll
            for (int nt = 0; nt < 4; nt++)
                bv[nt] = *(const float2*)(Bsb + (ks * 16 + n8b + nt) * BSEG + lane * 2);
#pragma unroll
            for (int mt = 0; mt < 4; mt++)
#pragma unroll
                for (int nt = 0; nt < 4; nt++)
                    mma_tf32(acc[mt][nt], &av[mt].x, &bv[nt].x);
        }

        if (more) {
            store_smem(cur ^ 1);
            __syncthreads();
            cur ^= 1;
        }
    }

    // ---- epilogue ----
    const int gid = lane >> 2, tig = lane & 3;
#pragma unroll
    for (int mt = 0; mt < 4; mt++) {
        int r0 = rowBase + (m16b + mt) * 16 + gid;
#pragma unroll
        for (int nt = 0; nt < 4; nt++) {
            int c0 = colBase + (n8b + nt) * 8 + tig * 2;
            float b0 = 0.f, b1 = 0.f;
            if (BIAS) { b0 = bias[c0]; b1 = bias[c0 + 1]; }
            float o0 = acc[mt][nt][0] + b0, o1 = acc[mt][nt][1] + b1;
            float o2 = acc[mt][nt][2] + b0, o3 = acc[mt][nt][3] + b1;
            if (RELU) {
                o0 = fmaxf(o0, 0.f); o1 = fmaxf(o1, 0.f);
                o2 = fmaxf(o2, 0.f); o3 = fmaxf(o3, 0.f);
            }
            if (r0 < Mr)     *(float2*)(Cmat + (size_t)r0 * Nc + c0)       = make_float2(o0, o1);
            if (r0 + 8 < Mr) *(float2*)(Cmat + (size_t)(r0 + 8) * Nc + c0) = make_float2(o2, o3);
        }
    }
}

// ---------------- text vector: masked mean pool ----------------
__global__ void k_textvec(const int* __restrict__ sentence, const float* __restrict__ mask,
                          const float* __restrict__ we, float* __restrict__ TEXTV)
{
    int b = blockIdx.x;
    int t = threadIdx.x;   // 192
    float4 acc = make_float4(0.f, 0.f, 0.f, 0.f);
    float msum = 0.f;
    for (int l = 0; l < L_; l++) {
        float w = mask[b * L_ + l];
        msum += w;
        int s = sentence[b * L_ + l];
        float4 f = *(const float4*)(we + (size_t)s * EMB_ + t * 4);
        acc.x += w * f.x; acc.y += w * f.y; acc.z += w * f.z; acc.w += w * f.w;
    }
    float inv = 1.f / (msum + 1e-9f);
    acc.x *= inv; acc.y *= inv; acc.z *= inv; acc.w *= inv;
    *(float4*)(TEXTV + b * EMB_ + t * 4) = acc;
}

// ---------------- build fused-gather row index ----------------
__global__ void k_buildidx(const int* __restrict__ nodes, int* __restrict__ IDX)
{
    int r = blockIdx.x * blockDim.x + threadIdx.x;
    if (r >= NLROWS) return;
    int b = r >> 12;
    int rem = r & 4095;
    int n = KS_ + (rem >> 3);
    int m = rem & 7;
    IDX[r] = nodes[(b * N_ + n) * M_ + m];
}

// ---------------- masked sum pool over M ----------------
__global__ void k_pool(const int* __restrict__ nodes, const float* __restrict__ nmask,
                       const float* __restrict__ ent, const float* __restrict__ ROWS,
                       float* __restrict__ X)
{
    int bn = blockIdx.x;          // 0..8191
    int t = threadIdx.x;          // 192
    int b = bn >> 10, n = bn & 1023;
    float4 acc = make_float4(0.f, 0.f, 0.f, 0.f);
    if (n < KS_) {
#pragma unroll
        for (int m = 0; m < M_; m++) {
            float w = nmask[bn * M_ + m];
            int e = nodes[bn * M_ + m];
            float4 f = *(const float4*)(ent + (size_t)e * EMB_ + t * 4);
            acc.x += w * f.x; acc.y += w * f.y; acc.z += w * f.z; acc.w += w * f.w;
        }
    } else {
        int rbase = (b * KS_ + (n - KS_)) * M_;
#pragma unroll
        for (int m = 0; m < M_; m++) {
            float w = nmask[bn * M_ + m];
            float4 f = *(const float4*)(ROWS + (size_t)(rbase + m) * EMB_ + t * 4);
            acc.x += w * f.x; acc.y += w * f.y; acc.z += w * f.z; acc.w += w * f.w;
        }
    }
    *(float4*)(X + (size_t)bn * EMB_ + t * 4) = acc;
}

// ---------------- build concat [text; NE] rows ----------------
__global__ void k_cat(const float* __restrict__ TEXTV, const float* __restrict__ NE,
                      float* __restrict__ CAT)
{
    int v = blockIdx.x * blockDim.x + threadIdx.x;
    if (v >= B_ * NN_ * 192) return;
    int row = v / 192, c = v % 192;
    int b = row / NN_, i = row % NN_;
    const float* src = (i == 0) ? (TEXTV + b * EMB_)
                                : (NE + (size_t)(b * N_ + i - 1) * EMB_);
    *(float4*)(CAT + (size_t)row * EMB_ + c * 4) = *(const float4*)(src + c * 4);
}

// ---------------- tiny projection ----------------
__global__ void k_tinyproj(const float* __restrict__ tab, const float* __restrict__ W,
                           float* __restrict__ out, int Kd)
{
    int t = blockIdx.x;
    int d = threadIdx.x;  // 256
    float s = 0.f;
    for (int j = 0; j < Kd; j++) s += tab[t * Kd + j] * W[j * D_ + d];
    out[t * D_ + d] = s;
}

// ---------------- pack Wq|Wk|Wv -> [L][256][768] ----------------
__global__ void k_packqkv(const float* __restrict__ wq, const float* __restrict__ wk,
                          const float* __restrict__ wv, float* __restrict__ W)
{
    int idx = blockIdx.x * blockDim.x + threadIdx.x;
    if (idx >= 2 * 256 * 768) return;
    int l = idx / (256 * 768);
    int rem = idx % (256 * 768);
    int k = rem / 768, j = rem % 768;
    const float* src = (j < 256) ? wq : (j < 512) ? wk : wv;
    W[idx] = src[(l * 256 + k) * 256 + (j & 255)];
}

// ---------------- add node-type embedding projection ----------------
__global__ void k_addtype(const int* __restrict__ ntypes, const float* __restrict__ TP,
                          float* __restrict__ Hf)
{
    int idx = blockIdx.x * blockDim.x + threadIdx.x;
    if (idx >= B_ * NN_ * D_) return;
    int row = idx >> 8, d = idx & 255;
    int b = row / NN_, i = row % NN_;
    int tc = ntypes[b * NN_ + i];
    Hf[idx] += TP[tc * D_ + d];
}

// ---------------- zero per-layer accumulators ----------------
__global__ void k_zero(unsigned* __restrict__ MXE, float* __restrict__ DEN,
                       float* __restrict__ AGG)
{
    int idx = blockIdx.x * blockDim.x + threadIdx.x;
    if (idx < B_ * NN_ * D_) AGG[idx] = 0.f;
    if (idx < B_ * NN_ * 4) { MXE[idx] = 0u; DEN[idx] = 0.f; }
}

// ---------------- edge logits + segment max (QKV packed, stride 768) ----------------
__global__ void k_logits(const float* __restrict__ QKV,
                         const int* __restrict__ edges, const int* __restrict__ etypes,
                         const float* __restrict__ KETl, float* __restrict__ LBUF,
                         unsigned* __restrict__ MXE)
{
    int gw = (blockIdx.x * blockDim.x + threadIdx.x) >> 5;
    int lane = threadIdx.x & 31;
    if (gw >= B_ * E_) return;
    int b = gw / E_, e = gw % E_;
    int src = edges[(b * 2) * E_ + e];
    int dst = edges[(b * 2 + 1) * E_ + e];
    int et = etypes[b * E_ + e];
    const float* q  = QKV + (size_t)(b * NN_ + dst) * 768;
    const float* kk = QKV + (size_t)(b * NN_ + src) * 768 + 256;
    const float* ke = KETl + et * D_;
    float p[4] = {0.f, 0.f, 0.f, 0.f};
#pragma unroll
    for (int s = 0; s < 8; s++) {
        int j = lane + 32 * s;
        p[s >> 1] += q[j] * (kk[j] + ke[j]);
    }
#pragma unroll
    for (int o = 16; o; o >>= 1) {
#pragma unroll
        for (int h = 0; h < 4; h++) p[h] += __shfl_xor_sync(~0u, p[h], o);
    }
    if (lane < 4) {
        float lg = p[lane] * 0.125f;   // 1/sqrt(64)
        LBUF[(size_t)gw * 4 + lane] = lg;
        atomicMax(&MXE[(b * NN_ + dst) * 4 + lane], fenc(lg));
    }
}

// ---------------- exp + segment sum ----------------
__global__ void k_exp(const int* __restrict__ edges, float* __restrict__ LBUF,
                      const unsigned* __restrict__ MXE, float* __restrict__ DEN)
{
    int idx = blockIdx.x * blockDim.x + threadIdx.x;
    if (idx >= B_ * E_ * 4) return;
    int h = idx & 3;
    int ge = idx >> 2;
    int b = ge / E_, e = ge % E_;
    int dst = edges[(b * 2 + 1) * E_ + e];
    float mx = fdec(MXE[(b * NN_ + dst) * 4 + h]);
    float ex = expf(LBUF[idx] - mx);
    LBUF[idx] = ex;
    atomicAdd(&DEN[(b * NN_ + dst) * 4 + h], ex);
}

// ---------------- weighted aggregate ----------------
__global__ void k_agg(const float* __restrict__ QKV, const int* __restrict__ edges,
                      const float* __restrict__ LBUF, const float* __restrict__ DEN,
                      float* __restrict__ AGG)
{
    int gw = (blockIdx.x * blockDim.x + threadIdx.x) >> 5;
    int lane = threadIdx.x & 31;
    if (gw >= B_ * E_) return;
    int b = gw / E_, e = gw % E_;
    int src = edges[(b * 2) * E_ + e];
    int dst = edges[(b * 2 + 1) * E_ + e];
    float alpha[4];
#pragma unroll
    for (int h = 0; h < 4; h++)
        alpha[h] = LBUF[(size_t)gw * 4 + h] / (DEN[(b * NN_ + dst) * 4 + h] + 1e-9f);
    const float* v = QKV + (size_t)(b * NN_ + src) * 768 + 512;
    float* agg = AGG + (size_t)(b * NN_ + dst) * D_;
#pragma unroll
    for (int s = 0; s < 8; s++) {
        int j = lane + 32 * s;
        atomicAdd(&agg[j], alpha[s >> 1] * v[j]);
    }
}

// ---------------- h = relu(h + agg) ----------------
__global__ void k_hupdate(float* __restrict__ Hf, const float* __restrict__ AGG)
{
    int idx = blockIdx.x * blockDim.x + threadIdx.x;
    if (idx >= B_ * NN_ * D_) return;
    Hf[idx] = fmaxf(Hf[idx] + AGG[idx], 0.f);
}

// ---------------- fold cls_w @ cls2_w into W2C, bias into B2 ----------------
__global__ void k_w2c(const float* __restrict__ cls_w, const float* __restrict__ cls_b,
                      const float* __restrict__ cls2_w, const float* __restrict__ cls2_b,
                      float* __restrict__ W2C, float* __restrict__ B2)
{
    int c = blockIdx.x;
    int tid = threadIdx.x;  // 256
    __shared__ __align__(16) float s2[EMB_];
    for (int e = tid; e < EMB_; e += 256) s2[e] = cls2_w[c * EMB_ + e];
    __syncthreads();
    for (int j = tid; j < 1280; j += 256) {
        const float* w = cls_w + (size_t)j * EMB_;
        float s = 0.f;
        for (int e4 = 0; e4 < EMB_ / 4; e4++) {
            float4 a = *(const float4*)(w + e4 * 4);
            float4 b = *(const float4*)(&s2[e4 * 4]);
            s += a.x * b.x + a.y * b.y + a.z * b.z + a.w * b.w;
        }
        W2C[c * 1280 + j] = s;
    }
    float p = 0.f;
    for (int e = tid; e < EMB_; e += 256) p += cls_b[e] * s2[e];
    __shared__ float red[256];
    red[tid] = p; __syncthreads();
    for (int s = 128; s; s >>= 1) { if (tid < s) red[tid] += red[tid + s]; __syncthreads(); }
    if (tid == 0) B2[c] = red[0] + cls2_b[c];
}

// ---------------- final output ----------------
__global__ void k_out(const float* __restrict__ Hf, const float* __restrict__ TEXTV,
                      const float* __restrict__ W2C, const float* __restrict__ B2,
                      float* __restrict__ out)
{
    int o = blockIdx.x;   // 400
    int b = o / C_, c = o % C_;
    int lane = threadIdx.x;  // 32
    const float* ctx = Hf + (size_t)(b * NN_) * D_;
    const float* lab = Hf + (size_t)(b * NN_ + 1 + c) * D_;
    const float* txt = TEXTV + b * EMB_;
    const float* w = W2C + c * 1280;
    float s = 0.f;
    for (int j = lane; j < 256; j += 32) s += ctx[j] * w[j];
    for (int j = lane; j < 256; j += 32) s += lab[j] * w[256 + j];
    for (int j = lane; j < 768; j += 32) s += txt[j] * w[512 + j];
#pragma unroll
    for (int off = 16; off; off >>= 1) s += __shfl_xor_sync(~0u, s, off);
    if (lane == 0) out[b * C_ + c] = s + B2[c];
}

// ---------------- host launch ----------------
static float* fsym(const void* s) { void* p = nullptr; cudaGetSymbolAddress(&p, s); return (float*)p; }

extern "C" void kernel_launch(void* const* d_in, const int* in_sizes, int n_in,
                              void* d_out, int out_size)
{
    const int*   sentence      = (const int*)  d_in[0];
    const float* mask          = (const float*)d_in[1];
    const int*   nodes         = (const int*)  d_in[2];
    const float* node_mask     = (const float*)d_in[3];
    const int*   node_types    = (const int*)  d_in[4];
    const int*   edges         = (const int*)  d_in[5];
    const int*   edge_types    = (const int*)  d_in[6];
    const float* word_embed    = (const float*)d_in[7];
    const float* entity_table  = (const float*)d_in[8];
    const float* type_table    = (const float*)d_in[9];
    const float* mlp_w1        = (const float*)d_in[10];
    const float* mlp_b1        = (const float*)d_in[11];
    const float* mlp_w2        = (const float*)d_in[12];
    const float* mlp_b2        = (const float*)d_in[13];
    const float* ntw_w         = (const float*)d_in[14];
    const float* proj_w        = (const float*)d_in[15];
    const float* proj_b        = (const float*)d_in[16];
    const float* type_proj_w   = (const float*)d_in[17];
    const float* edge_type_tab = (const float*)d_in[18];
    const float* gnn_wq        = (const float*)d_in[19];
    const float* gnn_wk        = (const float*)d_in[20];
    const float* gnn_wv        = (const float*)d_in[21];
    const float* gnn_we        = (const float*)d_in[22];
    const float* cls_w         = (const float*)d_in[23];
    const float* cls_b         = (const float*)d_in[24];
    const float* cls2_w        = (const float*)d_in[25];
    const float* cls2_b        = (const float*)d_in[26];
    float* out = (float*)d_out;

    float*    TEXTV = fsym(g_text);
    float*    ROWS  = fsym(g_rows);
    float*    HID   = fsym(g_hid);
    int*      IDX   = (int*)fsym(g_idx);
    float*    X     = fsym(g_X);
    float*    NE    = fsym(g_NE);
    float*    CAT   = fsym(g_CAT);
    float*    Hf    = fsym(g_H);
    float*    QKV   = fsym(g_QKV);
    float*    WQKV  = fsym(g_WQKV);
    float*    TP    = fsym(g_TP);
    float*    KET   = fsym(g_KET);
    float*    LBUF  = fsym(g_LBUF);
    unsigned* MXE   = (unsigned*)fsym(g_MXE);
    float*    DEN   = fsym(g_DEN);
    float*    AGG   = fsym(g_AGG);
    float*    W2C   = fsym(g_W2C);
    float*    B2    = fsym(g_B2);

    // allow >48KB dynamic smem (idempotent host-side attribute set, not captured)
    cudaFuncSetAttribute(gemm_tf32<true,  true>,  cudaFuncAttributeMaxDynamicSharedMemorySize, GSMEM);
    cudaFuncSetAttribute(gemm_tf32<false, true>,  cudaFuncAttributeMaxDynamicSharedMemorySize, GSMEM);
    cudaFuncSetAttribute(gemm_tf32<false, false>, cudaFuncAttributeMaxDynamicSharedMemorySize, GSMEM);

    // 1) text vector
    k_textvec<<<B_, 192>>>(sentence, mask, word_embed, TEXTV);

    // 2) MLP (two big TF32 GEMMs; gather fused into GEMM1 via row indices)
    k_buildidx<<<NLROWS / 256, 256>>>(nodes, IDX);
    gemm_tf32<true,  true><<<dim3(1024 / 128, NLROWS / 128), 256, GSMEM>>>(entity_table, mlp_w1, mlp_b1, HID, NLROWS, 1024, EMB_, IDX);
    gemm_tf32<false, true><<<dim3(EMB_ / 128, NLROWS / 128), 256, GSMEM>>>(HID, mlp_w2, mlp_b2, ROWS, NLROWS, EMB_, 1024, nullptr);

    // 3) masked pool over M, then ntw_w GEMM (pool commuted before linear map)
    k_pool<<<B_ * N_, 192>>>(nodes, node_mask, entity_table, ROWS, X);
    gemm_tf32<false, false><<<dim3(EMB_ / 128, (B_ * N_) / 128), 256, GSMEM>>>(X, ntw_w, nullptr, NE, B_ * N_, EMB_, EMB_, nullptr);

    // 4) concat + projection + type injection + weight packing
    k_cat<<<(B_ * NN_ * 192 + 255) / 256, 256>>>(TEXTV, NE, CAT);
    k_tinyproj<<<100, 256>>>(type_table, type_proj_w, TP, TD_);
    k_tinyproj<<<TD_, 256>>>(edge_type_tab, gnn_we, KET, TD_);
    k_tinyproj<<<TD_, 256>>>(edge_type_tab, gnn_we + TD_ * D_, KET + TD_ * D_, TD_);
    k_packqkv<<<(2 * 256 * 768 + 255) / 256, 256>>>(gnn_wq, gnn_wk, gnn_wv, WQKV);
    gemm_tf32<false, true><<<dim3(D_ / 128, (B_ * NN_ + 127) / 128), 256, GSMEM>>>(CAT, proj_w, proj_b, Hf, B_ * NN_, D_, EMB_, nullptr);
    k_addtype<<<(B_ * NN_ * D_ + 255) / 256, 256>>>(node_types, TP, Hf);

    // 5) GNN layers (QKV in one GEMM per layer)
    for (int l = 0; l < 2; l++) {
        gemm_tf32<false, false><<<dim3(768 / 128, (B_ * NN_ + 127) / 128), 256, GSMEM>>>(
            Hf, WQKV + (size_t)l * 256 * 768, nullptr, QKV, B_ * NN_, 768, D_, nullptr);
        k_zero<<<(B_ * NN_ * D_ + 255) / 256, 256>>>(MXE, DEN, AGG);
        k_logits<<<(B_ * E_ * 32) / 256, 256>>>(QKV, edges, edge_types, KET + l * TD_ * D_, LBUF, MXE);
        k_exp<<<(B_ * E_ * 4 + 255) / 256, 256>>>(edges, LBUF, MXE, DEN);
        k_agg<<<(B_ * E_ * 32) / 256, 256>>>(QKV, edges, LBUF, DEN, AGG);
        k_hupdate<<<(B_ * NN_ * D_ + 255) / 256, 256>>>(Hf, AGG);
    }

    // 6) fold classifier + final dot products
    k_w2c<<<C_, 256>>>(cls_w, cls_b, cls2_w, cls2_b, W2C, B2);
    k_out<<<B_ * C_, 32>>>(Hf, TEXTV, W2C, B2, out);
}